// round 1
// baseline (speedup 1.0000x reference)
#include <cuda_runtime.h>

// FractalEmbedding: out[b,l,d] = scale * sum_f julia_feats(token[b,l])[f] * W[d,f]
// B*L = 65536 tokens, EMBED_DIM = 1024, F = 16 (8 Julia steps x {zr,zi}).
//
// Strategy: store-bandwidth-bound problem (256 MB out). Each block handles 64
// tokens; each thread owns 4 consecutive dims with its W slice register-resident,
// packed into f32x2 pairs so the matvec runs on packed fma.rn.f32x2 (half the
// FMA-instruction count vs scalar FFMA, which would otherwise be the bottleneck).

#define THREADS 256
#define T_TOK   64

__device__ __forceinline__ unsigned long long pk2(float lo, float hi) {
    unsigned long long r;
    asm("mov.b64 %0, {%1, %2};" : "=l"(r) : "f"(lo), "f"(hi));
    return r;
}
__device__ __forceinline__ void upk2(float& lo, float& hi, unsigned long long v) {
    asm("mov.b64 {%0, %1}, %2;" : "=f"(lo), "=f"(hi) : "l"(v));
}
__device__ __forceinline__ unsigned long long mul2(unsigned long long a, unsigned long long b) {
    unsigned long long r;
    asm("mul.rn.f32x2 %0, %1, %2;" : "=l"(r) : "l"(a), "l"(b));
    return r;
}
__device__ __forceinline__ void fma2(unsigned long long& d, unsigned long long a, unsigned long long b) {
    asm("fma.rn.f32x2 %0, %1, %2, %0;" : "+l"(d) : "l"(a), "l"(b));
}

__global__ __launch_bounds__(THREADS, 2)
void fractal_embed_kernel(const int* __restrict__ tok,
                          const float2* __restrict__ ctab,
                          const float4* __restrict__ Wv,
                          const float* __restrict__ scale_p,
                          float4* __restrict__ out)
{
    __shared__ float sfeat[T_TOK][16];   // per-token features, scale pre-folded

    const int tid  = threadIdx.x;
    const int base = blockIdx.x * T_TOK;

    // --- Register-resident W slice: 4 rows (dims d0..d0+3) x 16 f, packed f32x2 ---
    const int d0 = tid * 4;
    unsigned long long wp[4][8];
#pragma unroll
    for (int j = 0; j < 4; ++j) {
        const float4* row = Wv + (size_t)(d0 + j) * 4;   // 16 floats = 4 float4
#pragma unroll
        for (int q = 0; q < 4; ++q) {
            float4 v = row[q];
            wp[j][2 * q]     = pk2(v.x, v.y);
            wp[j][2 * q + 1] = pk2(v.z, v.w);
        }
    }

    const float s = *scale_p;

    // --- Phase 1: threads 0..63 compute Julia features for this tile's tokens ---
    if (tid < T_TOK) {
        int t = tok[base + tid];
        float2 c = ctab[t];
        float zr = 0.f, zi = 0.f;
#pragma unroll
        for (int k = 0; k < 8; ++k) {
            float nr = zr * zr - zi * zi + c.x;
            float ni = 2.f * zr * zi + c.y;
            zr = nr; zi = ni;
            sfeat[tid][2 * k]     = zr * s;
            sfeat[tid][2 * k + 1] = zi * s;
        }
    }
    __syncthreads();

    // --- Phase 2: matvec per token; broadcast LDS of feats, packed FMAs, STG.128 ---
    for (int i = 0; i < T_TOK; ++i) {
        const float2* fp = reinterpret_cast<const float2*>(sfeat[i]);
        unsigned long long a0, a1, a2, a3;
        {
            float2 fv = fp[0];
            unsigned long long sp = pk2(fv.x, fv.y);
            a0 = mul2(sp, wp[0][0]);
            a1 = mul2(sp, wp[1][0]);
            a2 = mul2(sp, wp[2][0]);
            a3 = mul2(sp, wp[3][0]);
        }
#pragma unroll
        for (int p = 1; p < 8; ++p) {
            float2 fv = fp[p];
            unsigned long long sp = pk2(fv.x, fv.y);
            fma2(a0, sp, wp[0][p]);
            fma2(a1, sp, wp[1][p]);
            fma2(a2, sp, wp[2][p]);
            fma2(a3, sp, wp[3][p]);
        }
        float4 o;
        float lo, hi;
        upk2(lo, hi, a0); o.x = lo + hi;
        upk2(lo, hi, a1); o.y = lo + hi;
        upk2(lo, hi, a2); o.z = lo + hi;
        upk2(lo, hi, a3); o.w = lo + hi;
        out[(size_t)(base + i) * 256 + tid] = o;   // 1024 floats/token = 256 float4
    }
}

extern "C" void kernel_launch(void* const* d_in, const int* in_sizes, int n_in,
                              void* d_out, int out_size)
{
    const int*    tok  = (const int*)d_in[0];      // token_ids (B*L,) int32
    const float2* ctab = (const float2*)d_in[1];   // c_table (V, 2) f32
    const float4* Wv   = (const float4*)d_in[2];   // W (1024, 16) f32 row-major
    const float*  scl  = (const float*)d_in[3];    // scale scalar f32
    float4* out = (float4*)d_out;                  // (B, L, 1024) f32

    int n_tok  = in_sizes[0];        // 65536
    int blocks = n_tok / T_TOK;      // 1024
    fractal_embed_kernel<<<blocks, THREADS>>>(tok, ctab, Wv, scl, out);
}